// round 1
// baseline (speedup 1.0000x reference)
#include <cuda_runtime.h>
#include <math.h>

#define MM 48
#define LL 48
#define NN 256
#define NPAIR 1176   // 48*49/2 (m<=k)
#define NT 256
#define PPT 5        // ceil(1176/256)

// Scratch: suffix products per sample/site/pair (weight 2 baked in for m<k).
__device__ float g_suf[(size_t)NN * LL * NPAIR];   // ~57.8 MB, [n][l][p]
__device__ float g_thc[LL * MM];
__device__ float g_ths[LL * MM];

__global__ void theta_kernel(const float* __restrict__ theta) {
    int i = blockIdx.x * blockDim.x + threadIdx.x;
    if (i < LL * MM) {
        double s, c;
        sincos((double)theta[i], &s, &c);   // accurate trig of the f32 theta
        g_thc[i] = (float)c;
        g_ths[i] = (float)s;
    }
}

__global__ __launch_bounds__(NT) void zipper_kernel(
    const float* __restrict__ inp,      // (N,L)
    const float* __restrict__ coef,     // (M,)
    const float* __restrict__ rand_u,   // (L,N)
    float* __restrict__ out)            // N*L bits then N probs
{
    __shared__ float a_sh[LL][MM];
    __shared__ float b_sh[LL][MM];
    __shared__ float inp_sh[LL];
    __shared__ double g_sh[MM];
    __shared__ float x_sh[MM], y_sh[MM];
    __shared__ double red0[NT / 32], red1[NT / 32];
    __shared__ int bit_sh;
    __shared__ double scale_sh;

    const int n = blockIdx.x;
    const int tid = threadIdx.x;

    if (tid < LL) inp_sh[tid] = inp[n * LL + tid];
    if (tid < MM) g_sh[tid] = 1.0;
    __syncthreads();

    // ---- Phase 1: MPS components a=cos-part, b=sin-part, matching ref f32 rounding ----
    const float PI2F = (float)1.5707963267948966;   // fl32(pi/2), as JAX casts it
    for (int e = tid; e < LL * MM; e += NT) {
        int l = e / MM, m = e % MM;
        float km = (float)(m + 1) * PI2F;           // f32 like m_vals*(PI/2)
        float ang = inp_sh[l] * km;                 // f32 like ref
        double ds, dc;
        sincos((double)ang, &ds, &dc);              // exact trig of the f32 angle
        float ca = (float)dc, sa = (float)ds;
        float c = g_thc[e], s = g_ths[e];
        float cf = coef[m];
        a_sh[l][m] = cf * (c * ca - s * sa);        // p=0 row of R@emb
        b_sh[l][m] = cf * (s * ca + c * sa);        // p=1 row
    }
    __syncthreads();

    // ---- Pair (m<=k) assignment for this thread ----
    int pm[PPT], pk[PPT];
#pragma unroll
    for (int j = 0; j < PPT; j++) { pm[j] = 0; pk[j] = 0; }
#pragma unroll
    for (int j = 0; j < PPT; j++) {
        int p = tid + j * NT;
        if (p < NPAIR) {
            int m = 0, off = 0;
            while (off + (MM - m) <= p) { off += (MM - m); m++; }
            pm[j] = m;
            pk[j] = m + (p - off);
        }
    }

    // ---- Phase 2: suffix products of full-site dots, reverse scan ----
    float* sufn = g_suf + (size_t)n * (LL * NPAIR);
    {
        float run[PPT];
#pragma unroll
        for (int j = 0; j < PPT; j++)
            run[j] = (pm[j] == pk[j]) ? 1.0f : 2.0f;   // symmetry weight baked in
        for (int l = LL - 1; l >= 0; l--) {
            float* sufl = sufn + l * NPAIR;
#pragma unroll
            for (int j = 0; j < PPT; j++) {
                int p = tid + j * NT;
                if (p < NPAIR) {
                    sufl[p] = run[j];
                    float t = a_sh[l][pm[j]] * a_sh[l][pk[j]]
                            + b_sh[l][pm[j]] * b_sh[l][pk[j]];
                    run[j] *= t;
                }
            }
        }
    }

    // ---- Phase 3: sequential zipper over sites ----
    double denom0 = 0.0;   // valid in thread 0
    int Kexp = 0;          // power-of-2 renorm exponent (thread 0)
    for (int l = 0; l < LL; l++) {
        if (tid < MM) {
            double g = g_sh[tid];
            x_sh[tid] = (float)(g * (double)b_sh[l][tid]);  // bit=1 branch factor
            y_sh[tid] = (float)(g * (double)a_sh[l][tid]);  // bit=0 branch factor
        }
        __syncthreads();

        float s0 = 0.0f, s1 = 0.0f;
        const float* sufl = sufn + l * NPAIR;
#pragma unroll
        for (int j = 0; j < PPT; j++) {
            int p = tid + j * NT;
            if (p < NPAIR) {
                float suf = sufl[p];
                float xm = x_sh[pm[j]], xk = x_sh[pk[j]];
                float ym = y_sh[pm[j]], yk = y_sh[pk[j]];
                s1 = fmaf(xm * xk, suf, s1);
                s0 = fmaf(ym * yk, suf, s0);
            }
        }
        double d0 = (double)s0, d1 = (double)s1;
#pragma unroll
        for (int o = 16; o; o >>= 1) {
            d0 += __shfl_down_sync(0xffffffffu, d0, o);
            d1 += __shfl_down_sync(0xffffffffu, d1, o);
        }
        if ((tid & 31) == 0) { red0[tid >> 5] = d0; red1[tid >> 5] = d1; }
        __syncthreads();

        if (tid == 0) {
            double S0 = 0.0, S1 = 0.0;
#pragma unroll
            for (int w = 0; w < NT / 32; w++) { S0 += red0[w]; S1 += red1[w]; }
            double den = S0 + S1;                 // == inner(mps_cur) exactly
            if (l == 0) denom0 = den;
            float p1 = (float)(fabs(S1) / fabs(den));
            float u = rand_u[l * NN + n];
            int bit = (u < p1) ? 1 : 0;
            bit_sh = bit;
            out[n * LL + l] = (float)bit;
            // exact power-of-2 renorm so f32 x/y never underflow; p1 invariant
            double sc = bit ? S1 : S0;
            int k = 0;
            if (sc > 0.0) k = ilogb(sc) >> 1;
            Kexp += k;
            scale_sh = ldexp(1.0, -k);
        }
        __syncthreads();

        if (tid < MM) {
            double c = (double)(bit_sh ? b_sh[l][tid] : a_sh[l][tid]);
            g_sh[tid] = g_sh[tid] * c * scale_sh;
        }
    }
    __syncthreads();

    if (tid == 0) {
        double gs = 0.0;
#pragma unroll
        for (int m = 0; m < MM; m++) gs += g_sh[m];
        // inner(final) = (sum_m g_m)^2, undo renorm: true = stored * 2^Kexp
        double pmv = ldexp(gs * gs, 2 * Kexp) / fabs(denom0);
        out[NN * LL + n] = (float)pmv;
    }
}

extern "C" void kernel_launch(void* const* d_in, const int* in_sizes, int n_in,
                              void* d_out, int out_size) {
    const float* inp    = (const float*)d_in[0];   // (N,L)
    const float* theta  = (const float*)d_in[1];   // (L,M)
    const float* coef   = (const float*)d_in[2];   // (M,)
    const float* rand_u = (const float*)d_in[3];   // (L,N)
    float* out = (float*)d_out;

    theta_kernel<<<(LL * MM + 255) / 256, 256>>>(theta);
    zipper_kernel<<<NN, NT>>>(inp, coef, rand_u, out);
}

// round 2
// speedup vs baseline: 4.3556x; 4.3556x over previous
#include <cuda_runtime.h>
#include <math.h>

#define MM 48
#define LL 48
#define NN 256
#define NPAIR 1176   // 48*49/2 (m<=k)
#define NPAD 1280    // padded pair count (multiple of 256)
#define ZT 128       // zipper threads per CTA
#define ZPJ 10       // pairs per zipper thread (1280/128)
#define BT 256       // suffix kernel threads
#define BPJ 5        // pairs per suffix thread (1280/256)

// Scratch (static __device__ — allocation-free per harness rules)
__device__ float2 g_ab[(size_t)NN * LL * MM];        // (a,b) per (n,l,m)  ~4.7 MB
__device__ float  g_suf[(size_t)NN * LL * NPAD];     // suffix products    ~62.9 MB

// Accurate f32 sincos: Cody-Waite FMA range reduction + Taylor polys.
// |x| < ~80. Immune to --use_fast_math (no libm calls), ~1-2 ulp.
__device__ __forceinline__ void sincos_acc(float x, float* s, float* c) {
    float kf = rintf(x * 0.63661977236758134f);           // x * 2/pi
    int k = (int)kf;
    float r = fmaf(kf, -1.57079637050628662109375f, x);   // - k * fl32(pi/2)
    r = fmaf(kf, 4.37113882867379290e-8f, r);             // - k * lo correction
    float r2 = r * r;
    // sin(r) = r + r^3 * ps(r^2)
    float ps = fmaf(r2, 2.7557314297e-06f, -1.9841270114e-04f);
    ps = fmaf(r2, ps, 8.3333337680e-03f);
    ps = fmaf(r2, ps, -1.6666667163e-01f);
    float sr = fmaf(r * r2, ps, r);
    // cos(r) = (1 - 0.5 r^2) + r^4 * pc(r^2)
    float pc = fmaf(r2, -2.7557314297e-07f, 2.4760126951e-05f);
    pc = fmaf(r2, pc, -1.3888889225e-03f);
    pc = fmaf(r2, pc, 4.1666667908e-02f);
    float cr = fmaf(r2 * r2, pc, fmaf(r2, -0.5f, 1.0f));
    switch (k & 3) {
        case 0: *s = sr;  *c = cr;  break;
        case 1: *s = cr;  *c = -sr; break;
        case 2: *s = -sr; *c = -cr; break;
        default:*s = -cr; *c = sr;  break;
    }
}

// Kernel A: a,b per (n,l,m), matching reference f32 rounding of the angle.
__global__ void emb_kernel(const float* __restrict__ inp,
                           const float* __restrict__ theta,
                           const float* __restrict__ coef) {
    int i = blockIdx.x * blockDim.x + threadIdx.x;
    if (i >= NN * LL * MM) return;
    int m = i % MM;
    int t = i / MM;
    int l = t % LL;
    int n = t / LL;
    float km  = (float)(m + 1) * 1.57079637050628662109375f;  // f32 like ref
    float ang = inp[n * LL + l] * km;                          // f32 like ref
    float sa, ca; sincos_acc(ang, &sa, &ca);
    float st, ct; sincos_acc(theta[l * MM + m], &st, &ct);
    float cf = coef[m];
    float a = cf * (ct * ca - st * sa);   // p=0 row of R@emb
    float b = cf * (st * ca + ct * sa);   // p=1 row
    g_ab[(size_t)i] = make_float2(a, b);
}

// Kernel B: suffix products of full-site dots per pair, symmetry weight baked in.
__global__ __launch_bounds__(BT) void suffix_kernel() {
    __shared__ float2 ab[LL * MM];
    int n = blockIdx.x, tid = threadIdx.x;
    const float2* abg = g_ab + (size_t)n * (LL * MM);
    for (int e = tid; e < LL * MM; e += BT) ab[e] = abg[e];
    __syncthreads();

    int pm[BPJ], pk[BPJ];
    float run[BPJ];
#pragma unroll
    for (int j = 0; j < BPJ; j++) {
        int p = tid + BT * j;
        if (p < NPAIR) {
            int m = 0, off = 0;
            while (off + (MM - m) <= p) { off += MM - m; m++; }
            pm[j] = m; pk[j] = m + (p - off);
            run[j] = (pm[j] == pk[j]) ? 1.0f : 2.0f;
        } else { pm[j] = 0; pk[j] = 0; run[j] = 0.0f; }   // padded -> zero
    }
    float* sufn = g_suf + (size_t)n * (LL * NPAD);
    for (int l = LL - 1; l >= 0; l--) {
#pragma unroll
        for (int j = 0; j < BPJ; j++) {
            sufn[l * NPAD + tid + BT * j] = run[j];
            float2 vm = ab[l * MM + pm[j]];
            float2 vk = ab[l * MM + pk[j]];
            run[j] *= fmaf(vm.x, vk.x, vm.y * vk.y);
        }
    }
}

// Kernel C: zipper. One CTA (128 thr) per sample; all-f32 critical path,
// 2 barriers/step, redundant decision computation (no thread-0 serialization).
__global__ __launch_bounds__(ZT) void zipper_kernel(
    const float* __restrict__ rand_u,   // (L,N)
    float* __restrict__ out)            // N*L bits then N probs
{
    __shared__ float2 ab[LL * MM];
    __shared__ float2 xy[MM];
    __shared__ float u_sh[LL];
    __shared__ float part0[4], part1[4];
    __shared__ float gfin[MM];

    const int n = blockIdx.x, tid = threadIdx.x;
    const int wid = tid >> 5, lane = tid & 31;

    const float2* abg = g_ab + (size_t)n * (LL * MM);
#pragma unroll
    for (int e = tid; e < LL * MM; e += ZT) ab[e] = abg[e];
    if (tid < LL) u_sh[tid] = rand_u[tid * NN + n];

    // pair (m<=k) decode; padded pairs point at (0,0) but have suf==0
    int pmk[ZPJ];
#pragma unroll
    for (int j = 0; j < ZPJ; j++) {
        int p = tid + ZT * j;
        int m = 0, kk = 0;
        if (p < NPAIR) {
            int off = 0;
            while (off + (MM - m) <= p) { off += MM - m; m++; }
            kk = m + (p - off);
        }
        pmk[j] = m | (kk << 8);
    }
    const float* sufn = g_suf + (size_t)n * (LL * NPAD);
    float sufp[ZPJ];
#pragma unroll
    for (int j = 0; j < ZPJ; j++) sufp[j] = sufn[tid + ZT * j];   // l=0 row

    float g = 1.0f;        // per-mode prefix scalar (thread tid<48 owns mode tid)
    float denom0 = 1.0f;
    int Kexp = 0;          // power-of-2 renorm exponent (tracked by all threads)
    __syncthreads();

    for (int l = 0; l < LL; l++) {
        float2 abl;
        if (tid < MM) {
            abl = ab[l * MM + tid];
            xy[tid] = make_float2(g * abl.y, g * abl.x);  // x=g*b (bit1), y=g*a (bit0)
        }
        __syncthreads();   // bar1: xy ready

        // prefetch next step's suffix row (hides L2 latency off the chain)
        float nsuf[ZPJ];
        if (l + 1 < LL) {
#pragma unroll
            for (int j = 0; j < ZPJ; j++)
                nsuf[j] = sufn[(l + 1) * NPAD + tid + ZT * j];
        } else {
#pragma unroll
            for (int j = 0; j < ZPJ; j++) nsuf[j] = 0.0f;
        }

        float s0 = 0.0f, s1 = 0.0f;
#pragma unroll
        for (int j = 0; j < ZPJ; j++) {
            float2 vm = xy[pmk[j] & 0xFF];
            float2 vk = xy[pmk[j] >> 8];
            s1 = fmaf(vm.x * vk.x, sufp[j], s1);
            s0 = fmaf(vm.y * vk.y, sufp[j], s0);
        }
#pragma unroll
        for (int o = 16; o; o >>= 1) {
            s0 += __shfl_xor_sync(0xffffffffu, s0, o);
            s1 += __shfl_xor_sync(0xffffffffu, s1, o);
        }
        if (lane == 0) { part0[wid] = s0; part1[wid] = s1; }
        __syncthreads();   // bar2: warp partials ready

        // every thread computes the decision redundantly (identical values)
        float S0 = (part0[0] + part0[1]) + (part0[2] + part0[3]);
        float S1 = (part1[0] + part1[1]) + (part1[2] + part1[3]);
        float den = fabsf(S0 + S1);                    // inner(prefix-masked mps)
        float p1  = fabsf(S1) / den;
        int bit = (u_sh[l] < p1) ? 1 : 0;
        if (l == 0) denom0 = den;                      // true inner(mps), pre-renorm
        // exact power-of-2 renorm (p1 invariant, keeps g in f32 range)
        int eb = (__float_as_int(den) >> 23) & 0xFF;
        int k = (eb != 0) ? ((eb - 127) >> 1) : 0;
        Kexp += k;
        float scale = __int_as_float((127 - k) << 23); // 2^{-k}
        if (tid < MM) g = g * (bit ? abl.y : abl.x) * scale;
        if (tid == 0) out[n * LL + l] = (float)bit;    // off critical path
#pragma unroll
        for (int j = 0; j < ZPJ; j++) sufp[j] = nsuf[j];
    }

    if (tid < MM) gfin[tid] = g;
    __syncthreads();
    if (tid == 0) {
        double gs = 0.0;
#pragma unroll
        for (int m = 0; m < MM; m++) gs += (double)gfin[m];
        // inner(final) = (sum_m g)^2 * 2^(2*Kexp); P_m = that / inner(initial)
        double pmv = ldexp(gs * gs, 2 * Kexp) / (double)denom0;
        out[NN * LL + n] = (float)pmv;
    }
}

extern "C" void kernel_launch(void* const* d_in, const int* in_sizes, int n_in,
                              void* d_out, int out_size) {
    const float* inp    = (const float*)d_in[0];   // (N,L)
    const float* theta  = (const float*)d_in[1];   // (L,M)
    const float* coef   = (const float*)d_in[2];   // (M,)
    const float* rand_u = (const float*)d_in[3];   // (L,N)
    float* out = (float*)d_out;

    emb_kernel<<<(NN * LL * MM + 255) / 256, 256>>>(inp, theta, coef);
    suffix_kernel<<<NN, BT>>>();
    zipper_kernel<<<NN, ZT>>>(rand_u, out);
}

// round 3
// speedup vs baseline: 4.3781x; 1.0052x over previous
#include <cuda_runtime.h>
#include <math.h>

#define MM 48
#define LL 48
#define NN 256
#define NPAIR 1176        // 48*49/2 (m<=k)
#define NSLOT 1280        // 32 lanes * 40 slots (37 real + 3 pad per lane)
#define SUFV4 320         // NSLOT/4, float4 row stride

// Scratch (static __device__ — allocation-free per harness rules)
__device__ float2 g_ab[(size_t)NN * LL * MM];       // (a,b) per (n,l,m)  ~4.7 MB
__device__ float  g_suf[(size_t)NN * LL * NSLOT];   // suffix products    ~62.9 MB
__device__ float  g_thc[LL * MM];
__device__ float  g_ths[LL * MM];

// Accurate f32 sincos: Cody-Waite FMA range reduction + Taylor polys.
// |x| < ~80, ~1-2 ulp, immune to --use_fast_math (no libm).
__device__ __forceinline__ void sincos_acc(float x, float* s, float* c) {
    float kf = rintf(x * 0.63661977236758134f);           // x * 2/pi
    int k = (int)kf;
    float r = fmaf(kf, -1.57079637050628662109375f, x);   // - k * fl32(pi/2)
    r = fmaf(kf, 4.37113882867379290e-8f, r);             // - k * lo correction
    float r2 = r * r;
    float ps = fmaf(r2, 2.7557314297e-06f, -1.9841270114e-04f);
    ps = fmaf(r2, ps, 8.3333337680e-03f);
    ps = fmaf(r2, ps, -1.6666667163e-01f);
    float sr = fmaf(r * r2, ps, r);
    float pc = fmaf(r2, -2.7557314297e-07f, 2.4760126951e-05f);
    pc = fmaf(r2, pc, -1.3888889225e-03f);
    pc = fmaf(r2, pc, 4.1666667908e-02f);
    float cr = fmaf(r2 * r2, pc, fmaf(r2, -0.5f, 1.0f));
    switch (k & 3) {
        case 0: *s = sr;  *c = cr;  break;
        case 1: *s = cr;  *c = -sr; break;
        case 2: *s = -sr; *c = -cr; break;
        default:*s = -cr; *c = sr;  break;
    }
}

// Kernel 1: theta trig table (once, shared by all samples)
__global__ void theta_kernel(const float* __restrict__ theta) {
    int i = blockIdx.x * blockDim.x + threadIdx.x;
    if (i < LL * MM) {
        float s, c; sincos_acc(theta[i], &s, &c);
        g_thc[i] = c; g_ths[i] = s;
    }
}

// Kernel 2 (fused emb + suffix): per-sample CTA computes the a/b tile,
// writes it for the zipper, then reverse-scans suffix products of the
// full-site pair dots into the zipper's lane-chunked layout.
__global__ __launch_bounds__(256) void suffix_kernel(
    const float* __restrict__ inp, const float* __restrict__ coef) {
    __shared__ float2 ab[LL * MM];
    __shared__ float inp_sh[LL];
    const int n = blockIdx.x, tid = threadIdx.x;

    if (tid < LL) inp_sh[tid] = inp[n * LL + tid];
    __syncthreads();

    float2* abg = g_ab + (size_t)n * (LL * MM);
    const float PI2F = 1.57079637050628662109375f;  // fl32(pi/2)
    for (int e = tid; e < LL * MM; e += 256) {
        int l = e / MM, m = e % MM;
        float ang = inp_sh[l] * ((float)(m + 1) * PI2F);   // f32 like ref
        float sa, ca; sincos_acc(ang, &sa, &ca);
        float ct = g_thc[e], st = g_ths[e];
        float cf = coef[m];
        float2 v = make_float2(cf * (ct * ca - st * sa),   // a (p=0)
                               cf * (st * ca + ct * sa));  // b (p=1)
        ab[e] = v;
        abg[e] = v;
    }
    __syncthreads();

    // slot s = tid + 256*j ; zipper lane lz = s/40 owns pair 37*lz + (s%40)
    int pm[5], pk[5];
    float run[5];
#pragma unroll
    for (int j = 0; j < 5; j++) {
        int s = tid + 256 * j;
        int lz = s / 40, jj = s - lz * 40;
        int p = 37 * lz + jj;
        if (jj < 37 && p < NPAIR) {
            int m = 0, off = 0;
            while (off + (MM - m) <= p) { off += MM - m; m++; }
            pm[j] = m; pk[j] = m + (p - off);
            run[j] = (pm[j] == pk[j]) ? 1.0f : 2.0f;       // symmetry weight
        } else { pm[j] = 0; pk[j] = 0; run[j] = 0.0f; }    // pad -> 0
    }
    float* sufn = g_suf + (size_t)n * (LL * NSLOT);
    for (int l = LL - 1; l >= 0; l--) {
#pragma unroll
        for (int j = 0; j < 5; j++) {
            sufn[l * NSLOT + tid + 256 * j] = run[j];
            float2 vm = ab[l * MM + pm[j]];
            float2 vk = ab[l * MM + pk[j]];
            run[j] *= fmaf(vm.x, vk.x, vm.y * vk.y);
        }
    }
}

// Kernel 3: zipper, ONE WARP PER SAMPLE. No CTA barriers; one __syncwarp
// per step with double-buffered xy; warp-butterfly reduction; suf + ab
// rows prefetched one site ahead.
__global__ __launch_bounds__(32) void zipper_kernel(
    const float* __restrict__ rand_u,   // (L,N)
    float* __restrict__ out)            // N*L bits then N probs
{
    __shared__ float2 xys[128];         // 2 buffers x 64 slots (48 modes + pad)
    __shared__ float u_sh[LL];

    const int n = blockIdx.x, lane = threadIdx.x;
    const float2* abg = g_ab + (size_t)n * (LL * MM);
    const float4* sufv = reinterpret_cast<const float4*>(g_suf + (size_t)n * (LL * NSLOT));

    // init: u row, zero the pad slots of both xy buffers
    for (int e = lane; e < LL; e += 32) u_sh[e] = rand_u[e * NN + n];
    if (lane < 16) {
        xys[48 + lane]      = make_float2(0.f, 0.f);
        xys[64 + 48 + lane] = make_float2(0.f, 0.f);
    }

    // this lane's first pair (contiguous row-major chunk of 37)
    int m0 = 0, k0;
    {
        int p0 = 37 * lane, off = 0;
        while (off + (MM - m0) <= p0) { off += MM - m0; m0++; }
        k0 = m0 + (p0 - off);
    }

    // per-mode state: lane owns mode `lane`, and mode `lane+32` if lane<16
    float g0 = 1.0f;
    float g1 = (lane < 16) ? 1.0f : 0.0f;
    float2 abc0 = abg[lane];
    float2 abc1 = (lane < 16) ? abg[lane + 32] : make_float2(0.f, 0.f);

    float4 sufA[10], sufB[10];
#pragma unroll
    for (int j = 0; j < 10; j++) sufA[j] = sufv[10 * lane + j];   // row l=0

    int Kexp = 0;
    float denom0 = 1.0f;
    unsigned long long bits = 0ull;
    __syncwarp();

    auto stepf = [&](float4* cur, float4* nxt, int l) {
        float2* xb = xys + ((l & 1) << 6);
        xb[lane] = make_float2(g0 * abc0.y, g0 * abc0.x);   // x=g*b(bit1), y=g*a(bit0)
        if (lane < 16) xb[lane + 32] = make_float2(g1 * abc1.y, g1 * abc1.x);
        __syncwarp();

        // prefetch next site's suf row + ab row (off the chain)
        float2 abn0 = abc0, abn1 = abc1;
        if (l + 1 < LL) {
#pragma unroll
            for (int j = 0; j < 10; j++)
                nxt[j] = sufv[(size_t)(l + 1) * SUFV4 + 10 * lane + j];
            abn0 = abg[(l + 1) * MM + lane];
            if (lane < 16) abn1 = abg[(l + 1) * MM + lane + 32];
        }
        float un = u_sh[l];

        float s0 = 0.f, s1 = 0.f;
        int m = m0, k = k0;
#pragma unroll
        for (int j = 0; j < 37; j++) {
            float4 q = cur[j >> 2];
            float sf = ((j & 3) == 0) ? q.x : ((j & 3) == 1) ? q.y
                     : ((j & 3) == 2) ? q.z : q.w;
            float2 vm = xb[m], vk = xb[k];
            s1 = fmaf(vm.x * vk.x, sf, s1);
            s0 = fmaf(vm.y * vk.y, sf, s0);
            if (++k == MM) { ++m; k = m; }
        }
#pragma unroll
        for (int o = 16; o; o >>= 1) {
            s0 += __shfl_xor_sync(0xffffffffu, s0, o);
            s1 += __shfl_xor_sync(0xffffffffu, s1, o);
        }
        float den = fabsf(s0 + s1);            // inner of prefix-masked MPS
        float p1  = fabsf(s1) / den;
        int bit = (un < p1) ? 1 : 0;
        if (l == 0) denom0 = den;
        int eb = (__float_as_int(den) >> 23) & 0xFF;   // exact 2^k renorm
        int kk = eb ? (eb - 127) >> 1 : 0;
        Kexp += kk;
        float scale = __int_as_float((127 - kk) << 23);
        g0 = g0 * (bit ? abc0.y : abc0.x) * scale;
        g1 = g1 * (bit ? abc1.y : abc1.x) * scale;
        bits |= (unsigned long long)bit << l;
        abc0 = abn0; abc1 = abn1;
    };

    for (int l = 0; l < LL; l += 2) {
        stepf(sufA, sufB, l);
        stepf(sufB, sufA, l + 1);
    }

    // outputs: bits (identical in every lane) and P_m
    out[n * LL + lane] = (float)((bits >> lane) & 1ull);
    if (lane < 16) out[n * LL + 32 + lane] = (float)((bits >> (lane + 32)) & 1ull);

    float gs = g0 + g1;
#pragma unroll
    for (int o = 16; o; o >>= 1) gs += __shfl_xor_sync(0xffffffffu, gs, o);
    if (lane == 0) {
        double pmv = ldexp((double)gs * (double)gs, 2 * Kexp) / (double)denom0;
        out[NN * LL + n] = (float)pmv;
    }
}

extern "C" void kernel_launch(void* const* d_in, const int* in_sizes, int n_in,
                              void* d_out, int out_size) {
    const float* inp    = (const float*)d_in[0];   // (N,L)
    const float* theta  = (const float*)d_in[1];   // (L,M)
    const float* coef   = (const float*)d_in[2];   // (M,)
    const float* rand_u = (const float*)d_in[3];   // (L,N)
    float* out = (float*)d_out;

    theta_kernel<<<(LL * MM + 255) / 256, 256>>>(theta);
    suffix_kernel<<<NN, 256>>>(inp, coef);
    zipper_kernel<<<NN, 32>>>(rand_u, out);
}